// round 1
// baseline (speedup 1.0000x reference)
#include <cuda_runtime.h>
#include <cuda_bf16.h>

// Problem constants (fixed by the dataset)
#define Bc   4
#define Cc   16
#define Hc   256
#define Wc   256
#define HWc  (Hc * Wc)
#define Coc  16
#define Kc   9          // 3x3
#define INV_N (1.0f / (float)(Bc * Coc * HWc))

__global__ void zero_out_kernel(float* out) {
    if (threadIdx.x == 0) out[0] = 0.0f;
}

__global__ __launch_bounds__(256) void dcn_loss_kernel(
    const float* __restrict__ offsets,  // [B, 2K, H, W]
    const float* __restrict__ input,    // [B, C, H, W]
    const float* __restrict__ ker,      // [Co, C, 3, 3]
    const float* __restrict__ target,   // [B, Co, H, W]
    float* __restrict__ out)
{
    // Shared kernel weights, reordered: sker[(c*9 + kk)*16 + o]
    __shared__ float sker[Cc * Kc * Coc];
    for (int i = threadIdx.x; i < Cc * Kc * Coc; i += blockDim.x) {
        int o  = i & (Coc - 1);
        int ck = i >> 4;                 // c*9 + kk
        sker[i] = ker[o * (Cc * Kc) + ck];
    }
    __syncthreads();

    const int p  = blockIdx.x * 256 + threadIdx.x;   // 0 .. B*H*W-1
    const int b  = p >> 16;
    const int hw = p & (HWc - 1);
    const int h  = hw >> 8;
    const int w  = hw & (Wc - 1);

    const float* inB  = input   + b * Cc * HWc;
    const float* offB = offsets + b * 2 * Kc * HWc + hw;

    float acc[Coc];
    #pragma unroll
    for (int o = 0; o < Coc; o++) acc[o] = 0.0f;

    #pragma unroll
    for (int kk = 0; kk < Kc; kk++) {
        const float dy = __ldg(offB + (2 * kk)     * HWc);
        const float dx = __ldg(offB + (2 * kk + 1) * HWc);
        const float y = dy + (float)(h - 1 + kk / 3);
        const float x = dx + (float)(w - 1 + kk % 3);

        const float y0f = floorf(y), x0f = floorf(x);
        const float wy = y - y0f,  wx = x - x0f;
        const int y0 = (int)y0f,   x0 = (int)x0f;
        const int y1 = y0 + 1,     x1 = x0 + 1;

        const bool vy0 = ((unsigned)y0 < Hc);
        const bool vy1 = ((unsigned)y1 < Hc);
        const bool vx0 = ((unsigned)x0 < Wc);
        const bool vx1 = ((unsigned)x1 < Wc);

        const float w00 = (1.0f - wy) * (1.0f - wx) * (float)(vy0 && vx0);
        const float w01 = (1.0f - wy) * wx          * (float)(vy0 && vx1);
        const float w10 = wy          * (1.0f - wx) * (float)(vy1 && vx0);
        const float w11 = wy          * wx          * (float)(vy1 && vx1);

        const int cy0 = min(max(y0, 0), Hc - 1);
        const int cy1 = min(max(y1, 0), Hc - 1);
        const int cx0 = min(max(x0, 0), Wc - 1);
        const int cx1 = min(max(x1, 0), Wc - 1);
        const int i00 = cy0 * Wc + cx0;
        const int i01 = cy0 * Wc + cx1;
        const int i10 = cy1 * Wc + cx0;
        const int i11 = cy1 * Wc + cx1;

        #pragma unroll
        for (int c = 0; c < Cc; c++) {
            const float* ic = inB + c * HWc;
            const float s = w00 * __ldg(ic + i00) + w01 * __ldg(ic + i01)
                          + w10 * __ldg(ic + i10) + w11 * __ldg(ic + i11);

            const float4* k4 = (const float4*)(sker + (c * Kc + kk) * Coc);
            #pragma unroll
            for (int q = 0; q < 4; q++) {
                const float4 kv = k4[q];
                acc[4 * q + 0] += s * kv.x;
                acc[4 * q + 1] += s * kv.y;
                acc[4 * q + 2] += s * kv.z;
                acc[4 * q + 3] += s * kv.w;
            }
        }
    }

    // Per-pixel squared error vs target
    const float* tgt = target + b * Coc * HWc + hw;
    float local = 0.0f;
    #pragma unroll
    for (int o = 0; o < Coc; o++) {
        const float d = acc[o] - __ldg(tgt + o * HWc);
        local += d * d;
    }

    // Warp reduce
    #pragma unroll
    for (int s = 16; s > 0; s >>= 1)
        local += __shfl_xor_sync(0xFFFFFFFFu, local, s);

    __shared__ float red[8];
    if ((threadIdx.x & 31) == 0) red[threadIdx.x >> 5] = local;
    __syncthreads();
    if (threadIdx.x < 8) {
        float v = red[threadIdx.x];
        #pragma unroll
        for (int s = 4; s > 0; s >>= 1)
            v += __shfl_xor_sync(0xFFu, v, s);
        if (threadIdx.x == 0) atomicAdd(out, v * INV_N);
    }
}

extern "C" void kernel_launch(void* const* d_in, const int* in_sizes, int n_in,
                              void* d_out, int out_size) {
    const float* offsets = (const float*)d_in[0];
    const float* input   = (const float*)d_in[1];
    const float* ker     = (const float*)d_in[2];
    const float* target  = (const float*)d_in[3];
    float* out = (float*)d_out;

    zero_out_kernel<<<1, 32>>>(out);

    const int total  = Bc * HWc;           // 262144 pixels
    const int blocks = total / 256;        // 1024
    dcn_loss_kernel<<<blocks, 256>>>(offsets, input, ker, target, out);
}

// round 2
// speedup vs baseline: 1.1259x; 1.1259x over previous
#include <cuda_runtime.h>
#include <cuda_bf16.h>

// Problem constants (fixed by the dataset)
#define Bc   4
#define Cc   16
#define Hc   256
#define Wc   256
#define HWc  (Hc * Wc)
#define Coc  16
#define Kc   9          // 3x3
#define INV_N (1.0f / (float)(Bc * Coc * HWc))

// Tiling
#define TILE_W 32
#define TILE_H 8
#define PAD    7                      // 2 (tap reach) + 5 (offset budget)
#define ROWS   (TILE_H + 2 * PAD)     // 22
#define COLS   (TILE_W + 2 * PAD)     // 46
#define STRIDE 47                     // odd stride to spread banks
#define CH_STRIDE (ROWS * STRIDE)     // 1034 floats per channel
#define SKER_OFF  (Cc * CH_STRIDE)    // 16544
#define SMEM_FLOATS (SKER_OFF + Cc * Kc * Coc)
#define SMEM_BYTES  (SMEM_FLOATS * 4) // 75392 bytes

__global__ void zero_out_kernel(float* out) {
    if (threadIdx.x == 0) out[0] = 0.0f;
}

extern __shared__ float smem[];

__global__ __launch_bounds__(256) void dcn_loss_tile_kernel(
    const float* __restrict__ offsets,  // [B, 2K, H, W]
    const float* __restrict__ input,    // [B, C, H, W]
    const float* __restrict__ ker,      // [Co, C, 3, 3]
    const float* __restrict__ target,   // [B, Co, H, W]
    float* __restrict__ out)
{
    const int tid  = threadIdx.x;
    const int b    = blockIdx.z;
    const int rowLo = blockIdx.y * TILE_H - PAD;
    const int colLo = blockIdx.x * TILE_W - PAD;

    const float* inB = input + b * Cc * HWc;

    // ---- Stage input tile (+halo) for all channels; zero outside image ----
    #pragma unroll
    for (int c = 0; c < Cc; c++) {
        const float* ic = inB + c * HWc;
        float* sc = smem + c * CH_STRIDE;
        #pragma unroll
        for (int i0 = 0; i0 < ROWS * COLS; i0 += 256) {
            int i = i0 + tid;
            if (i < ROWS * COLS) {
                int ry = i / COLS;
                int rx = i - ry * COLS;
                int gy = rowLo + ry;
                int gx = colLo + rx;
                float v = 0.0f;
                if ((unsigned)gy < Hc && (unsigned)gx < Wc)
                    v = __ldg(ic + gy * Wc + gx);
                sc[ry * STRIDE + rx] = v;
            }
        }
    }

    // ---- Stage kernel weights, reordered: sker[(c*9 + kk)*16 + o] ----
    float* sker = smem + SKER_OFF;
    for (int i = tid; i < Cc * Kc * Coc; i += 256) {
        int o  = i & (Coc - 1);
        int ck = i >> 4;
        sker[i] = ker[o * (Cc * Kc) + ck];
    }
    __syncthreads();

    // ---- Per-thread pixel ----
    const int w  = blockIdx.x * TILE_W + (tid & (TILE_W - 1));
    const int h  = blockIdx.y * TILE_H + (tid >> 5);
    const int hw = h * Wc + w;

    const float* offB = offsets + b * 2 * Kc * HWc + hw;

    float acc[Coc];
    #pragma unroll
    for (int o = 0; o < Coc; o++) acc[o] = 0.0f;

    #pragma unroll
    for (int kk = 0; kk < Kc; kk++) {
        const float dy = __ldg(offB + (2 * kk)     * HWc);
        const float dx = __ldg(offB + (2 * kk + 1) * HWc);
        const float y = dy + (float)(h - 1 + kk / 3);
        const float x = dx + (float)(w - 1 + kk % 3);

        const float y0f = floorf(y), x0f = floorf(x);
        const float wy = y - y0f,  wx = x - x0f;
        const int y0 = (int)y0f,   x0 = (int)x0f;

        const int ry0 = y0 - rowLo;
        const int rx0 = x0 - colLo;

        if ((unsigned)ry0 <= (ROWS - 2) && (unsigned)rx0 <= (COLS - 2)) {
            // Fast path: all 4 taps live in the staged halo (zeros outside image)
            const float w00 = (1.0f - wy) * (1.0f - wx);
            const float w01 = (1.0f - wy) * wx;
            const float w10 = wy          * (1.0f - wx);
            const float w11 = wy          * wx;
            const float* sb = smem + ry0 * STRIDE + rx0;

            #pragma unroll
            for (int c = 0; c < Cc; c++) {
                const float* p = sb + c * CH_STRIDE;
                const float s = w00 * p[0]      + w01 * p[1]
                              + w10 * p[STRIDE] + w11 * p[STRIDE + 1];

                const float4* k4 = (const float4*)(sker + (c * Kc + kk) * Coc);
                #pragma unroll
                for (int q = 0; q < 4; q++) {
                    const float4 kv = k4[q];
                    acc[4 * q + 0] += s * kv.x;
                    acc[4 * q + 1] += s * kv.y;
                    acc[4 * q + 2] += s * kv.z;
                    acc[4 * q + 3] += s * kv.w;
                }
            }
        } else {
            // Rare fallback: exact global path with validity masking + clamped idx
            const int y1 = y0 + 1, x1 = x0 + 1;
            const bool vy0 = ((unsigned)y0 < Hc);
            const bool vy1 = ((unsigned)y1 < Hc);
            const bool vx0 = ((unsigned)x0 < Wc);
            const bool vx1 = ((unsigned)x1 < Wc);

            const float w00 = (1.0f - wy) * (1.0f - wx) * (float)(vy0 && vx0);
            const float w01 = (1.0f - wy) * wx          * (float)(vy0 && vx1);
            const float w10 = wy          * (1.0f - wx) * (float)(vy1 && vx0);
            const float w11 = wy          * wx          * (float)(vy1 && vx1);

            const int cy0 = min(max(y0, 0), Hc - 1);
            const int cy1 = min(max(y1, 0), Hc - 1);
            const int cx0 = min(max(x0, 0), Wc - 1);
            const int cx1 = min(max(x1, 0), Wc - 1);
            const int i00 = cy0 * Wc + cx0;
            const int i01 = cy0 * Wc + cx1;
            const int i10 = cy1 * Wc + cx0;
            const int i11 = cy1 * Wc + cx1;

            #pragma unroll
            for (int c = 0; c < Cc; c++) {
                const float* ic = inB + c * HWc;
                const float s = w00 * __ldg(ic + i00) + w01 * __ldg(ic + i01)
                              + w10 * __ldg(ic + i10) + w11 * __ldg(ic + i11);

                const float4* k4 = (const float4*)(sker + (c * Kc + kk) * Coc);
                #pragma unroll
                for (int q = 0; q < 4; q++) {
                    const float4 kv = k4[q];
                    acc[4 * q + 0] += s * kv.x;
                    acc[4 * q + 1] += s * kv.y;
                    acc[4 * q + 2] += s * kv.z;
                    acc[4 * q + 3] += s * kv.w;
                }
            }
        }
    }

    // ---- Per-pixel squared error vs target ----
    const float* tgt = target + b * Coc * HWc + hw;
    float local = 0.0f;
    #pragma unroll
    for (int o = 0; o < Coc; o++) {
        const float d = acc[o] - __ldg(tgt + o * HWc);
        local += d * d;
    }

    // Warp + block reduce, one atomic per block
    #pragma unroll
    for (int s = 16; s > 0; s >>= 1)
        local += __shfl_xor_sync(0xFFFFFFFFu, local, s);

    __shared__ float red[8];
    if ((tid & 31) == 0) red[tid >> 5] = local;
    __syncthreads();
    if (tid < 8) {
        float v = red[tid];
        #pragma unroll
        for (int s = 4; s > 0; s >>= 1)
            v += __shfl_xor_sync(0xFFu, v, s);
        if (tid == 0) atomicAdd(out, v * INV_N);
    }
}

extern "C" void kernel_launch(void* const* d_in, const int* in_sizes, int n_in,
                              void* d_out, int out_size) {
    const float* offsets = (const float*)d_in[0];
    const float* input   = (const float*)d_in[1];
    const float* ker     = (const float*)d_in[2];
    const float* target  = (const float*)d_in[3];
    float* out = (float*)d_out;

    static bool attr_set = false;
    if (!attr_set) {
        cudaFuncSetAttribute(dcn_loss_tile_kernel,
                             cudaFuncAttributeMaxDynamicSharedMemorySize,
                             SMEM_BYTES);
        attr_set = true;
    }

    zero_out_kernel<<<1, 32>>>(out);

    dim3 grid(Wc / TILE_W, Hc / TILE_H, Bc);   // 8 x 32 x 4 = 1024 blocks
    dcn_loss_tile_kernel<<<grid, 256, SMEM_BYTES>>>(offsets, input, ker, target, out);
}

// round 3
// speedup vs baseline: 1.4673x; 1.3032x over previous
#include <cuda_runtime.h>
#include <cuda_bf16.h>

// Problem constants (fixed by the dataset)
#define Bc   4
#define Cc   16
#define Hc   256
#define Wc   256
#define HWc  (Hc * Wc)
#define Coc  16
#define Kc   9
#define INV_N (1.0f / (float)(Bc * Coc * HWc))

// Tiling: 32x16 pixel tile, 256 threads, 2 pixels/thread (rows r and r+8)
#define TILE_W 32
#define TILE_H 16
#define PAD    6
#define ROWS   (TILE_H + 2 * PAD)     // 28
#define COLS   (TILE_W + 2 * PAD)     // 44
#define NSITES (ROWS * COLS)          // 1232
#define SITE_STRIDE 20                // floats per site (16 ch + 4 pad), 80B: 16B-aligned, bank-spread
#define SKER_OFF (NSITES * SITE_STRIDE)          // 24640 floats
#define SMEM_FLOATS (SKER_OFF + Kc * Cc * Coc)   // + 2304
#define SMEM_BYTES  (SMEM_FLOATS * 4)            // 107776 B

typedef unsigned long long ull;

__device__ __forceinline__ ull pack2(float a, float b) {
    ull r; asm("mov.b64 %0, {%1, %2};" : "=l"(r) : "f"(a), "f"(b)); return r;
}
__device__ __forceinline__ void ffma2(ull& d, ull a, ull b) {
    asm("fma.rn.f32x2 %0, %1, %2, %0;" : "+l"(d) : "l"(a), "l"(b));
}
__device__ __forceinline__ void unpack2(ull v, float& lo, float& hi) {
    asm("mov.b64 {%0, %1}, %2;" : "=f"(lo), "=f"(hi) : "l"(v));
}

__global__ void zero_out_kernel(float* out) {
    if (threadIdx.x == 0) out[0] = 0.0f;
}

extern __shared__ float smem[];

__global__ __launch_bounds__(256, 2) void dcn_loss_kernel(
    const float* __restrict__ offsets,  // [B, 18, H, W]
    const float* __restrict__ input,    // [B, 16, H, W]
    const float* __restrict__ ker,      // [16, 16, 3, 3]
    const float* __restrict__ target,   // [B, 16, H, W]
    float* __restrict__ out)
{
    const int tid = threadIdx.x;
    const int b   = blockIdx.z;
    const int rowBase = blockIdx.y * TILE_H;
    const int colBase = blockIdx.x * TILE_W;
    const int rowLo = rowBase - PAD;
    const int colLo = colBase - PAD;

    const float* inB = input + b * Cc * HWc;
    float* sIn  = smem;
    float* skw  = smem + SKER_OFF;

    // ---- Stage input tile, channel-major per site (zeros outside image) ----
    for (int i = tid; i < NSITES; i += 256) {
        const int ry = i / COLS;
        const int rx = i - ry * COLS;
        const int gy = rowLo + ry;
        const int gx = colLo + rx;
        const bool ok = ((unsigned)gy < Hc) && ((unsigned)gx < Wc);
        const float* src = inB + gy * Wc + gx;
        float* dst = sIn + i * SITE_STRIDE;
        #pragma unroll
        for (int q = 0; q < 4; q++) {
            float4 v;
            v.x = ok ? __ldg(src + (4 * q + 0) * HWc) : 0.0f;
            v.y = ok ? __ldg(src + (4 * q + 1) * HWc) : 0.0f;
            v.z = ok ? __ldg(src + (4 * q + 2) * HWc) : 0.0f;
            v.w = ok ? __ldg(src + (4 * q + 3) * HWc) : 0.0f;
            *(float4*)(dst + 4 * q) = v;
        }
    }

    // ---- Stage weights: skw[(kk*16 + c)*16 + o] ----
    for (int i = tid; i < Kc * Cc * Coc; i += 256) {
        const int o  = i & 15;
        const int ck = i >> 4;          // kk*16 + c
        const int kk = ck >> 4;
        const int c  = ck & 15;
        skw[i] = ker[o * (Cc * Kc) + c * Kc + kk];
    }
    __syncthreads();

    // ---- Two pixels per thread ----
    const int lane = tid & 31;
    const int r    = tid >> 5;
    const int wpx  = colBase + lane;
    const int ha   = rowBase + r;
    const int hb   = ha + 8;
    const int hwa  = ha * Wc + wpx;
    const int hwb  = hb * Wc + wpx;

    const float* offA = offsets + b * 2 * Kc * HWc + hwa;
    const float* offBp = offsets + b * 2 * Kc * HWc + hwb;

    ull acc2a[8], acc2b[8];
    #pragma unroll
    for (int j = 0; j < 8; j++) { acc2a[j] = 0ull; acc2b[j] = 0ull; }

    // Exact per-pixel fallback (rare: |offset| >= ~5)
    auto tap_generic = [&](float y, float x, ull* acc2, int kk) {
        const float y0f = floorf(y), x0f = floorf(x);
        const float wy = y - y0f, wx = x - x0f;
        const int y0 = (int)y0f, x0 = (int)x0f;
        const int y1 = y0 + 1, x1 = x0 + 1;
        const bool vy0 = ((unsigned)y0 < Hc), vy1 = ((unsigned)y1 < Hc);
        const bool vx0 = ((unsigned)x0 < Wc), vx1 = ((unsigned)x1 < Wc);
        const float w00 = (1.0f - wy) * (1.0f - wx) * (float)(vy0 && vx0);
        const float w01 = (1.0f - wy) * wx          * (float)(vy0 && vx1);
        const float w10 = wy          * (1.0f - wx) * (float)(vy1 && vx0);
        const float w11 = wy          * wx          * (float)(vy1 && vx1);
        const int cy0 = min(max(y0, 0), Hc - 1), cy1 = min(max(y1, 0), Hc - 1);
        const int cx0 = min(max(x0, 0), Wc - 1), cx1 = min(max(x1, 0), Wc - 1);
        const int i00 = cy0 * Wc + cx0, i01 = cy0 * Wc + cx1;
        const int i10 = cy1 * Wc + cx0, i11 = cy1 * Wc + cx1;
        #pragma unroll
        for (int c = 0; c < Cc; c++) {
            const float* ic = inB + c * HWc;
            const float s = w00 * __ldg(ic + i00) + w01 * __ldg(ic + i01)
                          + w10 * __ldg(ic + i10) + w11 * __ldg(ic + i11);
            const ull sx = pack2(s, s);
            const ulonglong2* kw = (const ulonglong2*)(skw + ((kk * Cc + c) << 4));
            const ulonglong2 k0 = kw[0], k1 = kw[1], k2 = kw[2], k3 = kw[3];
            ffma2(acc2[0], sx, k0.x); ffma2(acc2[1], sx, k0.y);
            ffma2(acc2[2], sx, k1.x); ffma2(acc2[3], sx, k1.y);
            ffma2(acc2[4], sx, k2.x); ffma2(acc2[5], sx, k2.y);
            ffma2(acc2[6], sx, k3.x); ffma2(acc2[7], sx, k3.y);
        }
    };

    for (int kk = 0; kk < Kc; kk++) {
        const int kr = kk / 3;
        const int kc = kk - 3 * kr;

        const float dya = __ldg(offA + (2 * kk) * HWc);
        const float dxa = __ldg(offA + (2 * kk + 1) * HWc);
        const float dyb = __ldg(offBp + (2 * kk) * HWc);
        const float dxb = __ldg(offBp + (2 * kk + 1) * HWc);

        const float ya = dya + (float)(ha - 1 + kr);
        const float xa = dxa + (float)(wpx - 1 + kc);
        const float yb = dyb + (float)(hb - 1 + kr);
        const float xb = dxb + (float)(wpx - 1 + kc);

        const float ya0f = floorf(ya), xa0f = floorf(xa);
        const float yb0f = floorf(yb), xb0f = floorf(xb);
        const float wya = ya - ya0f, wxa = xa - xa0f;
        const float wyb = yb - yb0f, wxb = xb - xb0f;

        const int ry0a = (int)ya0f - rowLo, rx0a = (int)xa0f - colLo;
        const int ry0b = (int)yb0f - rowLo, rx0b = (int)xb0f - colLo;

        const bool fa = ((unsigned)ry0a <= (ROWS - 2)) && ((unsigned)rx0a <= (COLS - 2));
        const bool fb = ((unsigned)ry0b <= (ROWS - 2)) && ((unsigned)rx0b <= (COLS - 2));

        if (fa && fb) {
            const float w00a = (1.0f - wya) * (1.0f - wxa);
            const float w01a = (1.0f - wya) * wxa;
            const float w10a = wya          * (1.0f - wxa);
            const float w11a = wya          * wxa;
            const float w00b = (1.0f - wyb) * (1.0f - wxb);
            const float w01b = (1.0f - wyb) * wxb;
            const float w10b = wyb          * (1.0f - wxb);
            const float w11b = wyb          * wxb;

            const float* pa = sIn + (ry0a * COLS + rx0a) * SITE_STRIDE;
            const float* pb = sIn + (ry0b * COLS + rx0b) * SITE_STRIDE;

            #pragma unroll
            for (int q = 0; q < 4; q++) {
                const float4 a00 = *(const float4*)(pa + 4 * q);
                const float4 a01 = *(const float4*)(pa + SITE_STRIDE + 4 * q);
                const float4 a10 = *(const float4*)(pa + COLS * SITE_STRIDE + 4 * q);
                const float4 a11 = *(const float4*)(pa + (COLS + 1) * SITE_STRIDE + 4 * q);
                float4 sa;
                sa.x = w00a * a00.x + w01a * a01.x + w10a * a10.x + w11a * a11.x;
                sa.y = w00a * a00.y + w01a * a01.y + w10a * a10.y + w11a * a11.y;
                sa.z = w00a * a00.z + w01a * a01.z + w10a * a10.z + w11a * a11.z;
                sa.w = w00a * a00.w + w01a * a01.w + w10a * a10.w + w11a * a11.w;

                const float4 b00 = *(const float4*)(pb + 4 * q);
                const float4 b01 = *(const float4*)(pb + SITE_STRIDE + 4 * q);
                const float4 b10 = *(const float4*)(pb + COLS * SITE_STRIDE + 4 * q);
                const float4 b11 = *(const float4*)(pb + (COLS + 1) * SITE_STRIDE + 4 * q);
                float4 sb;
                sb.x = w00b * b00.x + w01b * b01.x + w10b * b10.x + w11b * b11.x;
                sb.y = w00b * b00.y + w01b * b01.y + w10b * b10.y + w11b * b11.y;
                sb.z = w00b * b00.z + w01b * b01.z + w10b * b10.z + w11b * b11.z;
                sb.w = w00b * b00.w + w01b * b01.w + w10b * b10.w + w11b * b11.w;

                const float sav[4] = { sa.x, sa.y, sa.z, sa.w };
                const float sbv[4] = { sb.x, sb.y, sb.z, sb.w };
                const ulonglong2* kwq = (const ulonglong2*)(skw + ((kk * Cc + 4 * q) << 4));

                #pragma unroll
                for (int j = 0; j < 4; j++) {
                    const ull sxa = pack2(sav[j], sav[j]);
                    const ull sxb = pack2(sbv[j], sbv[j]);
                    const ulonglong2* kw = kwq + j * 4;
                    const ulonglong2 k0 = kw[0], k1 = kw[1], k2 = kw[2], k3 = kw[3];
                    ffma2(acc2a[0], sxa, k0.x); ffma2(acc2a[1], sxa, k0.y);
                    ffma2(acc2a[2], sxa, k1.x); ffma2(acc2a[3], sxa, k1.y);
                    ffma2(acc2a[4], sxa, k2.x); ffma2(acc2a[5], sxa, k2.y);
                    ffma2(acc2a[6], sxa, k3.x); ffma2(acc2a[7], sxa, k3.y);
                    ffma2(acc2b[0], sxb, k0.x); ffma2(acc2b[1], sxb, k0.y);
                    ffma2(acc2b[2], sxb, k1.x); ffma2(acc2b[3], sxb, k1.y);
                    ffma2(acc2b[4], sxb, k2.x); ffma2(acc2b[5], sxb, k2.y);
                    ffma2(acc2b[6], sxb, k3.x); ffma2(acc2b[7], sxb, k3.y);
                }
            }
        } else {
            tap_generic(ya, xa, acc2a, kk);
            tap_generic(yb, xb, acc2b, kk);
        }
    }

    // ---- Squared error vs target for both pixels ----
    const float* ta = target + b * Coc * HWc + hwa;
    const float* tb = target + b * Coc * HWc + hwb;
    float local = 0.0f;
    #pragma unroll
    for (int j = 0; j < 8; j++) {
        float lo, hi;
        unpack2(acc2a[j], lo, hi);
        float d0 = lo - __ldg(ta + (2 * j) * HWc);
        float d1 = hi - __ldg(ta + (2 * j + 1) * HWc);
        local += d0 * d0 + d1 * d1;
        unpack2(acc2b[j], lo, hi);
        d0 = lo - __ldg(tb + (2 * j) * HWc);
        d1 = hi - __ldg(tb + (2 * j + 1) * HWc);
        local += d0 * d0 + d1 * d1;
    }

    // ---- Warp + block reduce, one atomic per block ----
    #pragma unroll
    for (int s = 16; s > 0; s >>= 1)
        local += __shfl_xor_sync(0xFFFFFFFFu, local, s);

    __shared__ float red[8];
    if ((tid & 31) == 0) red[tid >> 5] = local;
    __syncthreads();
    if (tid < 8) {
        float v = red[tid];
        #pragma unroll
        for (int s = 4; s > 0; s >>= 1)
            v += __shfl_xor_sync(0xFFu, v, s);
        if (tid == 0) atomicAdd(out, v * INV_N);
    }
}

extern "C" void kernel_launch(void* const* d_in, const int* in_sizes, int n_in,
                              void* d_out, int out_size) {
    const float* offsets = (const float*)d_in[0];
    const float* input   = (const float*)d_in[1];
    const float* ker     = (const float*)d_in[2];
    const float* target  = (const float*)d_in[3];
    float* out = (float*)d_out;

    static bool attr_set = false;
    if (!attr_set) {
        cudaFuncSetAttribute(dcn_loss_kernel,
                             cudaFuncAttributeMaxDynamicSharedMemorySize,
                             SMEM_BYTES);
        attr_set = true;
    }

    zero_out_kernel<<<1, 32>>>(out);

    dim3 grid(Wc / TILE_W, Hc / TILE_H, Bc);   // 8 x 16 x 4 = 512 blocks
    dcn_loss_kernel<<<grid, 256, SMEM_BYTES>>>(offsets, input, ker, target, out);
}